// round 9
// baseline (speedup 1.0000x reference)
#include <cuda_runtime.h>
#include <cuda_bf16.h>
#include <cstdint>

#define NUM_EXPERTS 16
#define DIM 1024
#define THREADS 256
#define NWARP 8
#define GRID 296
#define DC 16                  // dims per pipeline stage
#define NCH (DIM / DC)         // 64 chunks
#define TOK_PER_WARP 32
#define XPITCH_B 80            // token row pitch (16B-aligned; r*80 mod 128 distinct)
#define STAGE_B (TOK_PER_WARP * XPITCH_B)   // 2560
#define NSTAGE 2
#define EPITCH_B 80            // epilogue scratch row pitch

// W layout: expert-major [e][d], row pitch padded for bank-quad spread.
#define WPITCH_B 4128                        // 4096 + 32 (16B-aligned)
#define W_BYTES  (NUM_EXPERTS * WPITCH_B)    // 66048
#define B_OFF_B  W_BYTES                     // bias, 64B
#define X_OFF_B  66176                       // 128B aligned
#define SMEM_BYTES (X_OFF_B + NWARP * NSTAGE * STAGE_B)   // 107136 -> 2 CTAs/SM

typedef unsigned long long ull;

__device__ __forceinline__ void ffma2(ull& acc, ull a, ull b) {
    asm("fma.rn.f32x2 %0, %1, %2, %0;" : "+l"(acc) : "l"(a), "l"(b));
}

__device__ __forceinline__ void stage_cp(uint32_t xwarp, const float* xg,
                                         int stage, int c, int lane) {
    // 32 tokens x 16 dims (2KB): 4 lanes cover one token's 64B run.
    const uint32_t dst0 = xwarp + (uint32_t)(stage * STAGE_B);
#pragma unroll
    for (int k = 0; k < 4; k++) {
        int i = lane + (k << 5);
        int t = i >> 2;          // token within tile
        int j = i & 3;           // 16B slot within 64B run
        const float* src = xg + (size_t)t * DIM + c * DC + j * 4;
        uint32_t dst = dst0 + (uint32_t)(t * XPITCH_B + j * 16);
        asm volatile("cp.async.cg.shared.global [%0], [%1], 16;\n"
                     :: "r"(dst), "l"(src));
    }
}

__global__ __launch_bounds__(THREADS, 2)
void gating_kernel(const float* __restrict__ x,
                   const float* __restrict__ W,
                   const float* __restrict__ b,
                   float* __restrict__ out,
                   int T /* total tokens */) {
    extern __shared__ float smem[];
    float* b_s = smem + B_OFF_B / 4;

    const int tid  = threadIdx.x;
    const int wid  = tid >> 5;
    const int lane = tid & 31;
    const int eg   = lane >> 3;      // expert group: owns experts eg + 4q
    const int ts   = lane & 7;       // token slot: owns tokens ts + 8k, k=0..3
    const int ntiles = T / TOK_PER_WARP;                 // 2048
    const int tt = blockIdx.x + (int)gridDim.x * wid;    // balanced warp-tile id
    const bool active = (tt < ntiles);

    const uint32_t smem_u32 = (uint32_t)__cvta_generic_to_shared(smem);
    const uint32_t xwarp = smem_u32 + (uint32_t)(X_OFF_B + wid * NSTAGE * STAGE_B);
    const float* xg = x + (size_t)tt * TOK_PER_WARP * DIM;

    // Prefetch stage 0 (warp-private smem; safe across the block barrier).
    if (active) {
        stage_cp(xwarp, xg, 0, 0, lane);
        asm volatile("cp.async.commit_group;\n" ::: "memory");
    }

    // Stage W (direct copy, padded rows) + bias while stage 0 is in flight.
    for (int i = tid; i < NUM_EXPERTS * DIM; i += THREADS) {
        int e = i >> 10;
        int d = i & (DIM - 1);
        *reinterpret_cast<float*>(reinterpret_cast<char*>(smem) +
                                  (uint32_t)e * WPITCH_B + (uint32_t)d * 4) = W[i];
    }
    if (tid < NUM_EXPERTS) b_s[tid] = b[tid];
    __syncthreads();
    if (!active) return;

    // Per-lane bases.
    uint32_t wq_base[4];
#pragma unroll
    for (int q = 0; q < 4; q++)
        wq_base[q] = smem_u32 + (uint32_t)(eg + 4 * q) * WPITCH_B;
    uint32_t xrow[4];
#pragma unroll
    for (int k = 0; k < 4; k++)
        xrow[k] = xwarp + (uint32_t)((ts + 8 * k) * XPITCH_B);

    ull acc[4][4];   // [token k][expert slot q], f32x2 over (even,odd) dims
#pragma unroll
    for (int k = 0; k < 4; k++)
#pragma unroll
        for (int q = 0; q < 4; q++) acc[k][q] = 0ULL;

    for (int c = 0; c < NCH; c++) {
        __syncwarp();   // all lanes done reading the buffer we're about to refill
        if (c + 1 < NCH) {
            stage_cp(xwarp, xg, (c + 1) & 1, c + 1, lane);
        }
        asm volatile("cp.async.commit_group;\n" ::: "memory");
        asm volatile("cp.async.wait_group 1;\n" ::: "memory");  // stage c ready
        __syncwarp();

        const uint32_t xoff = (uint32_t)((c & 1) * STAGE_B);
        const uint32_t woff = (uint32_t)(c * DC * 4);   // byte offset of dim base
#pragma unroll
        for (int j = 0; j < DC / 4; j++) {
            ull w0[4], w1[4];
            const uint32_t wdj = woff + (uint32_t)(j * 16);
#pragma unroll
            for (int q = 0; q < 4; q++) {
                asm("ld.shared.v2.b64 {%0, %1}, [%2];"
                    : "=l"(w0[q]), "=l"(w1[q]) : "r"(wq_base[q] + wdj));
            }
#pragma unroll
            for (int k = 0; k < 4; k++) {
                ull xx0, xx1;
                asm("ld.shared.v2.b64 {%0, %1}, [%2];"
                    : "=l"(xx0), "=l"(xx1)
                    : "r"(xrow[k] + xoff + (uint32_t)(j * 16)));
#pragma unroll
                for (int q = 0; q < 4; q++) {
                    ffma2(acc[k][q], xx0, w0[q]);
                    ffma2(acc[k][q], xx1, w1[q]);
                }
            }
        }
    }

    // ---- epilogue: reduce f32x2 halves, transpose to token-major via smem ----
    __syncwarp();
#pragma unroll
    for (int k = 0; k < 4; k++) {
        uint32_t row = xwarp + (uint32_t)((ts + 8 * k) * EPITCH_B);
#pragma unroll
        for (int q = 0; q < 4; q++) {
            float lo = __uint_as_float((uint32_t)acc[k][q]);
            float hi = __uint_as_float((uint32_t)(acc[k][q] >> 32));
            float s = lo + hi;
            asm volatile("st.shared.f32 [%0], %1;"
                         :: "r"(row + (uint32_t)((eg + 4 * q) * 4)), "f"(s));
        }
    }
    __syncwarp();

    float logit[NUM_EXPERTS];
    {
        uint32_t myrow = xwarp + (uint32_t)(lane * EPITCH_B);
#pragma unroll
        for (int q = 0; q < 4; q++) {
            asm("ld.shared.v4.f32 {%0, %1, %2, %3}, [%4];"
                : "=f"(logit[4 * q]), "=f"(logit[4 * q + 1]),
                  "=f"(logit[4 * q + 2]), "=f"(logit[4 * q + 3])
                : "r"(myrow + (uint32_t)(q * 16)));
        }
    }
#pragma unroll
    for (int e = 0; e < NUM_EXPERTS; e++) logit[e] += b_s[e];

    float m = logit[0];
#pragma unroll
    for (int e = 1; e < NUM_EXPERTS; e++) m = fmaxf(m, logit[e]);

    float sum = 0.0f;
#pragma unroll
    for (int e = 0; e < NUM_EXPERTS; e++) {
        float w = __expf(logit[e] - m);
        logit[e] = w;
        sum += w;
    }
    const float inv = __fdividef(1.0f, sum);
#pragma unroll
    for (int e = 0; e < NUM_EXPERTS; e++) logit[e] *= inv;

    // top-2 (strict > keeps lowest index on ties, matching jax top_k)
    float v1 = -1.0f, v2 = -1.0f;
    int i1 = 0, i2 = 0;
#pragma unroll
    for (int e = 0; e < NUM_EXPERTS; e++) {
        float w = logit[e];
        if (w > v1) { v2 = v1; i2 = i1; v1 = w; i1 = e; }
        else if (w > v2) { v2 = w; i2 = e; }
    }

    const size_t t = (size_t)tt * TOK_PER_WARP + lane;
    float* outg = out;                                   // gated  [E, T]
    float* outw = out + (size_t)NUM_EXPERTS * T;         // weights[E, T]
#pragma unroll
    for (int e = 0; e < NUM_EXPERTS; e++) {
        float g = (e == i1) ? v1 : ((e == i2) ? v2 : 0.0f);
        outg[(size_t)e * T + t] = g;
        outw[(size_t)e * T + t] = logit[e];
    }
}

extern "C" void kernel_launch(void* const* d_in, const int* in_sizes, int n_in,
                              void* d_out, int out_size) {
    const float* x = (const float*)d_in[0];
    const float* W = (const float*)d_in[1];
    const float* b = (const float*)d_in[2];
    float* out = (float*)d_out;

    const int T = in_sizes[0] / DIM;           // 65536 tokens

    cudaFuncSetAttribute(gating_kernel,
                         cudaFuncAttributeMaxDynamicSharedMemorySize, SMEM_BYTES);
    gating_kernel<<<GRID, THREADS, SMEM_BYTES>>>(x, W, b, out, T);
}

// round 10
// speedup vs baseline: 1.1286x; 1.1286x over previous
#include <cuda_runtime.h>
#include <cuda.h>
#include <cuda_bf16.h>
#include <cstdint>

#define NUM_EXPERTS 16
#define DIM 1024
#define THREADS 512
#define NWARP 16
#define GRID 148
#define DC 32                  // dims per pipeline stage
#define NCH (DIM / DC)         // 32 chunks
#define TOK_PER_WARP 32
#define NSTAGE 2
#define STAGE_B 4096           // 32 tokens x 32 dims x 4B (SW128-swizzled)
#define EPITCH_B 80            // epilogue scratch row pitch

// W layout: expert-major [e][d], row pitch padded for bank-quad spread.
#define WPITCH_B 4128                        // 4096 + 32 (16B-aligned)
#define W_BYTES  (NUM_EXPERTS * WPITCH_B)    // 66048
#define B_OFF_B  W_BYTES                     // bias, 64B
#define MBAR_OFF (W_BYTES + 64)              // 16 warps x 16B = 256B
#define X_OFF_B  66560                       // 1024-aligned (65*1024) for SW128
#define SMEM_BYTES (X_OFF_B + NWARP * NSTAGE * STAGE_B)   // 197632

typedef unsigned long long ull;

__device__ __forceinline__ void ffma2(ull& acc, ull a, ull b) {
    asm("fma.rn.f32x2 %0, %1, %2, %0;" : "+l"(acc) : "l"(a), "l"(b));
}

__device__ __forceinline__ void mbar_wait(uint32_t bar, uint32_t parity) {
    uint32_t done;
    asm volatile(
        "{\n\t.reg .pred p;\n\t"
        "mbarrier.try_wait.parity.acquire.cta.shared::cta.b64 p, [%1], %2;\n\t"
        "selp.b32 %0, 1, 0, p;\n\t}"
        : "=r"(done) : "r"(bar), "r"(parity) : "memory");
    if (!done) {
        asm volatile(
            "{\n\t.reg .pred P1;\n\t"
            "WL_%=:\n\t"
            "mbarrier.try_wait.parity.acquire.cta.shared::cta.b64 P1, [%0], %1, 0x989680;\n\t"
            "@P1 bra.uni WD_%=;\n\t"
            "bra.uni WL_%=;\n\t"
            "WD_%=:\n\t}"
            :: "r"(bar), "r"(parity) : "memory");
    }
}

__global__ __launch_bounds__(THREADS, 1)
void gating_kernel(const float* __restrict__ W,
                   const float* __restrict__ b,
                   float* __restrict__ out,
                   int T,
                   const __grid_constant__ CUtensorMap tmap) {
    extern __shared__ float smem[];
    float* b_s = smem + B_OFF_B / 4;

    const int tid  = threadIdx.x;
    const int wid  = tid >> 5;
    const int lane = tid & 31;
    const int eg   = lane >> 3;      // expert group: owns experts eg + 4q
    const int ts   = lane & 7;       // token slot: owns tokens ts + 8k, k=0..3
    const int ntiles = T / TOK_PER_WARP;                 // 2048
    const int tt = blockIdx.x + (int)gridDim.x * wid;    // balanced warp-tile id
    const bool active = (tt < ntiles);

    const uint32_t smem_u32 = (uint32_t)__cvta_generic_to_shared(smem);
    const uint32_t mbar  = smem_u32 + (uint32_t)(MBAR_OFF + wid * 16);
    const uint32_t xwarp = smem_u32 + (uint32_t)(X_OFF_B + wid * NSTAGE * STAGE_B);
    const int tok0 = tt * TOK_PER_WARP;

    // Init this warp's two mbarriers, then issue stage 0 TMA (lane 0).
    if (lane == 0) {
        asm volatile("mbarrier.init.shared.b64 [%0], 1;" :: "r"(mbar) : "memory");
        asm volatile("mbarrier.init.shared.b64 [%0], 1;" :: "r"(mbar + 8) : "memory");
        asm volatile("fence.proxy.async.shared::cta;" ::: "memory");
        if (active) {
            asm volatile("mbarrier.arrive.expect_tx.shared.b64 _, [%0], %1;"
                         :: "r"(mbar), "r"((uint32_t)STAGE_B) : "memory");
            asm volatile(
                "cp.async.bulk.tensor.2d.shared::cta.global.tile.mbarrier::complete_tx::bytes "
                "[%0], [%1, {%2, %3}], [%4];"
                :: "r"(xwarp), "l"(&tmap), "r"(0), "r"(tok0), "r"(mbar) : "memory");
        }
    }

    // Stage W (direct copy, padded rows) + bias while stage 0 is in flight.
    for (int i = tid; i < NUM_EXPERTS * DIM; i += THREADS) {
        int e = i >> 10;
        int d = i & (DIM - 1);
        *reinterpret_cast<float*>(reinterpret_cast<char*>(smem) +
                                  (uint32_t)e * WPITCH_B + (uint32_t)d * 4) = W[i];
    }
    if (tid < NUM_EXPERTS) b_s[tid] = b[tid];
    __syncthreads();
    if (!active) return;

    // Per-lane bases.
    uint32_t wq_base[4];
#pragma unroll
    for (int q = 0; q < 4; q++)
        wq_base[q] = smem_u32 + (uint32_t)(eg + 4 * q) * WPITCH_B;
    uint32_t xrow[4];
#pragma unroll
    for (int k = 0; k < 4; k++)
        xrow[k] = xwarp + (uint32_t)((ts + 8 * k) * 128);

    ull acc[4][4];   // [token k][expert slot q], f32x2 over (even,odd) dims
#pragma unroll
    for (int k = 0; k < 4; k++)
#pragma unroll
        for (int q = 0; q < 4; q++) acc[k][q] = 0ULL;

    for (int c = 0; c < NCH; c++) {
        __syncwarp();   // all lanes done reading the buffer we're about to refill
        if (c + 1 < NCH && lane == 0) {
            uint32_t bar = mbar + ((c + 1) & 1) * 8;
            asm volatile("mbarrier.arrive.expect_tx.shared.b64 _, [%0], %1;"
                         :: "r"(bar), "r"((uint32_t)STAGE_B) : "memory");
            asm volatile(
                "cp.async.bulk.tensor.2d.shared::cta.global.tile.mbarrier::complete_tx::bytes "
                "[%0], [%1, {%2, %3}], [%4];"
                :: "r"(xwarp + (uint32_t)(((c + 1) & 1) * STAGE_B)), "l"(&tmap),
                   "r"((c + 1) * DC), "r"(tok0), "r"(bar) : "memory");
        }
        mbar_wait(mbar + (c & 1) * 8, (uint32_t)((c >> 1) & 1));

        const uint32_t xoff = (uint32_t)((c & 1) * STAGE_B);
        const uint32_t woff = (uint32_t)(c * DC * 4);   // byte offset of dim base
#pragma unroll
        for (int j = 0; j < DC / 4; j++) {
            ull w0[4], w1[4];
            const uint32_t wdj = woff + (uint32_t)(j * 16);
#pragma unroll
            for (int q = 0; q < 4; q++) {
                asm("ld.shared.v2.b64 {%0, %1}, [%2];"
                    : "=l"(w0[q]), "=l"(w1[q]) : "r"(wq_base[q] + wdj));
            }
            const uint32_t slot = (uint32_t)(((j ^ ts) & 7) << 4);  // SW128 swizzle
#pragma unroll
            for (int k = 0; k < 4; k++) {
                ull xx0, xx1;
                asm("ld.shared.v2.b64 {%0, %1}, [%2];"
                    : "=l"(xx0), "=l"(xx1)
                    : "r"(xrow[k] + xoff + slot));
#pragma unroll
                for (int q = 0; q < 4; q++) {
                    ffma2(acc[k][q], xx0, w0[q]);
                    ffma2(acc[k][q], xx1, w1[q]);
                }
            }
        }
    }

    // ---- epilogue: reduce f32x2 halves, transpose to token-major via smem ----
    __syncwarp();
#pragma unroll
    for (int k = 0; k < 4; k++) {
        uint32_t row = xwarp + (uint32_t)((ts + 8 * k) * EPITCH_B);
#pragma unroll
        for (int q = 0; q < 4; q++) {
            float lo = __uint_as_float((uint32_t)acc[k][q]);
            float hi = __uint_as_float((uint32_t)(acc[k][q] >> 32));
            float s = lo + hi;
            asm volatile("st.shared.f32 [%0], %1;"
                         :: "r"(row + (uint32_t)((eg + 4 * q) * 4)), "f"(s));
        }
    }
    __syncwarp();

    float logit[NUM_EXPERTS];
    {
        uint32_t myrow = xwarp + (uint32_t)(lane * EPITCH_B);
#pragma unroll
        for (int q = 0; q < 4; q++) {
            asm("ld.shared.v4.f32 {%0, %1, %2, %3}, [%4];"
                : "=f"(logit[4 * q]), "=f"(logit[4 * q + 1]),
                  "=f"(logit[4 * q + 2]), "=f"(logit[4 * q + 3])
                : "r"(myrow + (uint32_t)(q * 16)));
        }
    }
#pragma unroll
    for (int e = 0; e < NUM_EXPERTS; e++) logit[e] += b_s[e];

    float m = logit[0];
#pragma unroll
    for (int e = 1; e < NUM_EXPERTS; e++) m = fmaxf(m, logit[e]);

    float sum = 0.0f;
#pragma unroll
    for (int e = 0; e < NUM_EXPERTS; e++) {
        float w = __expf(logit[e] - m);
        logit[e] = w;
        sum += w;
    }
    const float inv = __fdividef(1.0f, sum);
#pragma unroll
    for (int e = 0; e < NUM_EXPERTS; e++) logit[e] *= inv;

    // top-2 (strict > keeps lowest index on ties, matching jax top_k)
    float v1 = -1.0f, v2 = -1.0f;
    int i1 = 0, i2 = 0;
#pragma unroll
    for (int e = 0; e < NUM_EXPERTS; e++) {
        float w = logit[e];
        if (w > v1) { v2 = v1; i2 = i1; v1 = w; i1 = e; }
        else if (w > v2) { v2 = w; i2 = e; }
    }

    const size_t t = (size_t)tok0 + lane;
    float* outg = out;                                   // gated  [E, T]
    float* outw = out + (size_t)NUM_EXPERTS * T;         // weights[E, T]
#pragma unroll
    for (int e = 0; e < NUM_EXPERTS; e++) {
        float g = (e == i1) ? v1 : ((e == i2) ? v2 : 0.0f);
        outg[(size_t)e * T + t] = g;
        outw[(size_t)e * T + t] = logit[e];
    }
}

typedef CUresult (*PFN_encodeTiled)(
    CUtensorMap*, CUtensorMapDataType, cuuint32_t, void*,
    const cuuint64_t*, const cuuint64_t*, const cuuint32_t*, const cuuint32_t*,
    CUtensorMapInterleave, CUtensorMapSwizzle, CUtensorMapL2promotion,
    CUtensorMapFloatOOBfill);

extern "C" void kernel_launch(void* const* d_in, const int* in_sizes, int n_in,
                              void* d_out, int out_size) {
    const float* x = (const float*)d_in[0];
    const float* W = (const float*)d_in[1];
    const float* b = (const float*)d_in[2];
    float* out = (float*)d_out;

    const int T = in_sizes[0] / DIM;           // 65536 tokens

    // Resolve cuTensorMapEncodeTiled via the runtime (no -lcuda link needed).
    static PFN_encodeTiled encode_fn = nullptr;
    if (!encode_fn) {
        void* fp = nullptr;
        cudaDriverEntryPointQueryResult st;
        cudaGetDriverEntryPoint("cuTensorMapEncodeTiled", &fp,
                                cudaEnableDefault, &st);
        encode_fn = (PFN_encodeTiled)fp;
    }

    CUtensorMap tmap;
    {
        cuuint64_t gdims[2]    = {(cuuint64_t)DIM, (cuuint64_t)T};
        cuuint64_t gstrides[1] = {(cuuint64_t)DIM * 4};
        cuuint32_t box[2]      = {DC, TOK_PER_WARP};
        cuuint32_t estr[2]     = {1, 1};
        encode_fn(&tmap, CU_TENSOR_MAP_DATA_TYPE_FLOAT32, 2, (void*)x,
                  gdims, gstrides, box, estr,
                  CU_TENSOR_MAP_INTERLEAVE_NONE, CU_TENSOR_MAP_SWIZZLE_128B,
                  CU_TENSOR_MAP_L2_PROMOTION_L2_128B,
                  CU_TENSOR_MAP_FLOAT_OOB_FILL_NONE);
    }

    cudaFuncSetAttribute(gating_kernel,
                         cudaFuncAttributeMaxDynamicSharedMemorySize, SMEM_BYTES);
    gating_kernel<<<GRID, THREADS, SMEM_BYTES>>>(W, b, out, T, tmap);
}